// round 15
// baseline (speedup 1.0000x reference)
#include <cuda_runtime.h>
#include <cuda_bf16.h>
#include <math.h>
#include <cstdint>

#define D_MODEL 2048
#define S_LEN   2048
#define BATCH   2
#define NROWS   (BATCH * S_LEN)   // 4096
#define N_HEADS 16
#define D_HEAD  128

// ---------------- scratch (alloc-free rule: __device__ globals) ----------------
__device__ __nv_bfloat16 g_Xh [(size_t)NROWS * D_MODEL];
__device__ __nv_bfloat16 g_Xl [(size_t)NROWS * D_MODEL];
__device__ __nv_bfloat16 g_Qh [(size_t)NROWS * D_MODEL];
__device__ __nv_bfloat16 g_Ql [(size_t)NROWS * D_MODEL];
__device__ __nv_bfloat16 g_Kh [(size_t)NROWS * D_MODEL];
__device__ __nv_bfloat16 g_Kl [(size_t)NROWS * D_MODEL];
__device__ __nv_bfloat16 g_Vh [(size_t)NROWS * D_MODEL];
__device__ __nv_bfloat16 g_Vl [(size_t)NROWS * D_MODEL];
__device__ __nv_bfloat16 g_AVh[(size_t)NROWS * D_MODEL];
__device__ __nv_bfloat16 g_AVl[(size_t)NROWS * D_MODEL];
// transposed weight splits: [4][N=2048][K=2048], order: Wq, Wk, Wv, Wo
__device__ __nv_bfloat16 g_Wth[(size_t)4 * D_MODEL * D_MODEL];
__device__ __nv_bfloat16 g_Wtl[(size_t)4 * D_MODEL * D_MODEL];

// ---------------- PTX helpers (valid on plain sm_103 target) ----------------
__device__ __forceinline__ uint32_t smem_u32(const void* p) {
    uint32_t a;
    asm("{ .reg .u64 t; cvta.to.shared.u64 t, %1; cvt.u32.u64 %0, t; }" : "=r"(a) : "l"(p));
    return a;
}
#define SWZ128(off) ((off) ^ (((off) >> 3) & 0x70))
#define SWZ64(off)  ((off) ^ (((off) >> 3) & 0x30))

__device__ __forceinline__ void cp_async16(uint32_t saddr, const void* gaddr) {
    asm volatile("cp.async.cg.shared.global [%0], [%1], 16;\n" :: "r"(saddr), "l"(gaddr));
}
#define CP_COMMIT() asm volatile("cp.async.commit_group;\n" ::: "memory")
#define CP_WAIT0()  asm volatile("cp.async.wait_group 0;\n" ::: "memory")
#define CP_WAIT1()  asm volatile("cp.async.wait_group 1;\n" ::: "memory")
#define CP_WAIT3()  asm volatile("cp.async.wait_group 3;\n" ::: "memory")

__device__ __forceinline__ void ldmx4(uint32_t* r, uint32_t addr) {
    asm volatile("ldmatrix.sync.aligned.m8n8.x4.shared.b16 {%0,%1,%2,%3}, [%4];"
        : "=r"(r[0]), "=r"(r[1]), "=r"(r[2]), "=r"(r[3]) : "r"(addr));
}
__device__ __forceinline__ void ldmx4t(uint32_t* r, uint32_t addr) {
    asm volatile("ldmatrix.sync.aligned.m8n8.x4.trans.shared.b16 {%0,%1,%2,%3}, [%4];"
        : "=r"(r[0]), "=r"(r[1]), "=r"(r[2]), "=r"(r[3]) : "r"(addr));
}
// non-volatile — pure register op, lets ptxas interleave independent MMAs.
__device__ __forceinline__ void mma16816(float* d, const uint32_t* a, const uint32_t* b) {
    asm("mma.sync.aligned.m16n8k16.row.col.f32.bf16.bf16.f32 "
        "{%0,%1,%2,%3}, {%4,%5,%6,%7}, {%8,%9}, {%0,%1,%2,%3};"
        : "+f"(d[0]), "+f"(d[1]), "+f"(d[2]), "+f"(d[3])
        : "r"(a[0]), "r"(a[1]), "r"(a[2]), "r"(a[3]), "r"(b[0]), "r"(b[1]));
}
__device__ __forceinline__ float ex2f(float x) {
    float y;
    asm("ex2.approx.f32 %0, %1;" : "=f"(y) : "f"(x));
    return y;
}
__device__ __forceinline__ void split_pack(float a, float b, uint32_t& h, uint32_t& l) {
    __nv_bfloat16 ha = __float2bfloat16(a), hb = __float2bfloat16(b);
    __nv_bfloat162 th, tl;
    th.x = ha; th.y = hb;
    tl.x = __float2bfloat16(a - __bfloat162float(ha));
    tl.y = __float2bfloat16(b - __bfloat162float(hb));
    h = *(uint32_t*)&th;
    l = *(uint32_t*)&tl;
}

// ---------------- LayerNorm + bf16 split: one block per row ----------------
__global__ __launch_bounds__(256) void ln_split_kernel(
    const float* __restrict__ X, const float* __restrict__ gam,
    const float* __restrict__ bet, __nv_bfloat16* __restrict__ Xh,
    __nv_bfloat16* __restrict__ Xl)
{
    int row = blockIdx.x;
    const float4* x4 = (const float4*)(X + (size_t)row * D_MODEL);
    const float4* g4 = (const float4*)gam;
    const float4* b4 = (const float4*)bet;
    int tid = threadIdx.x;

    float4 v0 = x4[tid];
    float4 v1 = x4[tid + 256];
    float s  = v0.x + v0.y + v0.z + v0.w + v1.x + v1.y + v1.z + v1.w;
    float ss = v0.x*v0.x + v0.y*v0.y + v0.z*v0.z + v0.w*v0.w
             + v1.x*v1.x + v1.y*v1.y + v1.z*v1.z + v1.w*v1.w;

    #pragma unroll
    for (int off = 16; off; off >>= 1) {
        s  += __shfl_xor_sync(0xffffffffu, s,  off);
        ss += __shfl_xor_sync(0xffffffffu, ss, off);
    }
    __shared__ float rs[8], rss[8];
    __shared__ float s_mean, s_rstd;
    int w = tid >> 5, l = tid & 31;
    if (l == 0) { rs[w] = s; rss[w] = ss; }
    __syncthreads();
    if (tid == 0) {
        float t = 0.f, tt = 0.f;
        #pragma unroll
        for (int i = 0; i < 8; i++) { t += rs[i]; tt += rss[i]; }
        float mean = t * (1.f / D_MODEL);
        float var  = tt * (1.f / D_MODEL) - mean * mean;
        s_mean = mean;
        s_rstd = rsqrtf(var + 1e-5f);
    }
    __syncthreads();
    float mean = s_mean, rstd = s_rstd;

    float4 g0 = g4[tid], g1 = g4[tid + 256];
    float4 c0 = b4[tid], c1 = b4[tid + 256];
    float r[8];
    r[0] = (v0.x - mean) * rstd * g0.x + c0.x;
    r[1] = (v0.y - mean) * rstd * g0.y + c0.y;
    r[2] = (v0.z - mean) * rstd * g0.z + c0.z;
    r[3] = (v0.w - mean) * rstd * g0.w + c0.w;
    r[4] = (v1.x - mean) * rstd * g1.x + c1.x;
    r[5] = (v1.y - mean) * rstd * g1.y + c1.y;
    r[6] = (v1.z - mean) * rstd * g1.z + c1.z;
    r[7] = (v1.w - mean) * rstd * g1.w + c1.w;

    uint32_t h0, l0, h1, l1, h2, l2, h3, l3;
    split_pack(r[0], r[1], h0, l0);
    split_pack(r[2], r[3], h1, l1);
    split_pack(r[4], r[5], h2, l2);
    split_pack(r[6], r[7], h3, l3);
    size_t base = (size_t)row * D_MODEL;
    uint2 vh0 = {h0, h1}, vl0 = {l0, l1}, vh1 = {h2, h3}, vl1 = {l2, l3};
    *(uint2*)(Xh + base + tid * 4)         = vh0;
    *(uint2*)(Xh + base + (tid + 256) * 4) = vh1;
    *(uint2*)(Xl + base + tid * 4)         = vl0;
    *(uint2*)(Xl + base + (tid + 256) * 4) = vl1;
}

// ---------------- weight transpose + split (all 4 weights, grid.z selects) ----------------
__global__ __launch_bounds__(256) void transpose_split_kernel(
    const float* __restrict__ W0, const float* __restrict__ W1,
    const float* __restrict__ W2, const float* __restrict__ W3,
    __nv_bfloat16* __restrict__ Th, __nv_bfloat16* __restrict__ Tl)
{
    __shared__ float t[32][33];
    int wsel = blockIdx.z;
    const float* W = (wsel == 0) ? W0 : (wsel == 1) ? W1 : (wsel == 2) ? W2 : W3;
    size_t obase = (size_t)wsel * D_MODEL * D_MODEL;
    int bx = blockIdx.x * 32;   // n0
    int by = blockIdx.y * 32;   // k0
    int tx = threadIdx.x & 31, ty = threadIdx.x >> 5;
    #pragma unroll
    for (int r = 0; r < 4; r++)
        t[ty + r * 8][tx] = W[(size_t)(by + ty + r * 8) * D_MODEL + bx + tx];
    __syncthreads();
    #pragma unroll
    for (int r = 0; r < 4; r++) {
        float v = t[tx][ty + r * 8];
        __nv_bfloat16 h = __float2bfloat16(v);
        size_t idx = obase + (size_t)(bx + ty + r * 8) * D_MODEL + by + tx;
        Th[idx] = h;
        Tl[idx] = __float2bfloat16(v - __bfloat162float(h));
    }
}

// ---------------- HMMA bf16x3 GEMM core: CTA 128x256, warp tile 64x64, BK=32 ----------------
#define TILE_A 8192                         // 128 rows x 64B
#define TILE_BB 16384                       // 256 rows x 64B
#define GDEPTH 4
#define STAGE_BYTES (2 * TILE_A + 2 * TILE_BB)   // 48KB: Ah|Al|Bh|Bl
#define GEMM_SMEM (GDEPTH * STAGE_BYTES)         // 192KB
#define NKITER 64                           // 2048 / 32

template <int SPLIT>
__device__ __forceinline__ void gemm_core(
    uint32_t sbase,
    const __nv_bfloat16* Ah, const __nv_bfloat16* Al,
    const __nv_bfloat16* Bh, const __nv_bfloat16* Bl,
    const float* bias, float* C,
    __nv_bfloat16* Ch, __nv_bfloat16* Cl,
    int bx, int by)
{
    int tid  = threadIdx.x;
    int wid  = tid >> 5;
    int lane = tid & 31;
    int wm = wid & 1;            // 2 warps in m
    int wn = wid >> 1;           // 4 warps in n (64 each)

    float acc[4][8][4];          // [mt][n8 block][frag]
    #pragma unroll
    for (int i = 0; i < 4; i++)
        #pragma unroll
        for (int j = 0; j < 8; j++)
            #pragma unroll
            for (int k = 0; k < 4; k++) acc[i][j][k] = 0.f;

    int lr = lane & 7, g = lane >> 3;
    int a_row = wm * 64 + ((g & 1) << 3) + lr;
    int a_col = (g >> 1) << 4;
    int b_rowc = ((g >> 1) << 3) + lr;     // + wn*64 + nt*16
    int b_col = (g & 1) << 4;

    auto issue = [&](int it) {
        int k0 = it * 32;
        int s  = it & (GDEPTH - 1);
        uint32_t sa = sbase + s * STAGE_BYTES;
        #pragma unroll
        for (int j = 0; j < 2; j++) {        // A: 512 16B chunks per split
            int c = tid + j * 256;
            int r = c >> 2, c16 = c & 3;
            uint32_t off = SWZ64((uint32_t)(r * 64 + c16 * 16));
            size_t aoff = (size_t)(by + r) * D_MODEL + k0 + c16 * 8;
            cp_async16(sa + off,          Ah + aoff);
            cp_async16(sa + TILE_A + off, Al + aoff);
        }
        #pragma unroll
        for (int j = 0; j < 4; j++) {        // B: 1024 16B chunks per split
            int c = tid + j * 256;
            int r = c >> 2, c16 = c & 3;
            uint32_t off = SWZ64((uint32_t)(r * 64 + c16 * 16));
            size_t boff = (size_t)(bx + r) * D_MODEL + k0 + c16 * 8;
            cp_async16(sa + 2 * TILE_A + off,           Bh + boff);
            cp_async16(sa + 2 * TILE_A + TILE_BB + off, Bl + boff);
        }
        CP_COMMIT();
    };

    issue(0); issue(1); issue(2);

    for (int i = 0; i < NKITER; i++) {
        if (i + 3 < NKITER) issue(i + 3); else CP_COMMIT();
        CP_WAIT3();
        __syncthreads();

        int s = i & (GDEPTH - 1);
        uint32_t sa = sbase + s * STAGE_BYTES;

        #pragma unroll
        for (int ks = 0; ks < 2; ks++) {
            uint32_t ahf[4][4], alf[4][4], bhf[4][4], blf[4][4];
            #pragma unroll
            for (int mt = 0; mt < 4; mt++) {
                uint32_t off = SWZ64((uint32_t)((a_row + mt * 16) * 64 + ks * 32 + a_col));
                ldmx4(ahf[mt], sa + off);
                ldmx4(alf[mt], sa + TILE_A + off);
            }
            #pragma unroll
            for (int nt = 0; nt < 4; nt++) {
                uint32_t off = SWZ64((uint32_t)((wn * 64 + nt * 16 + b_rowc) * 64 + ks * 32 + b_col));
                ldmx4(bhf[nt], sa + 2 * TILE_A + off);
                ldmx4(blf[nt], sa + 2 * TILE_A + TILE_BB + off);
            }
            // three sweeps of 32 independent MMAs each
            #pragma unroll
            for (int mt = 0; mt < 4; mt++)
                #pragma unroll
                for (int nt = 0; nt < 4; nt++) {
                    mma16816(acc[mt][nt * 2],     ahf[mt], bhf[nt]);
                    mma16816(acc[mt][nt * 2 + 1], ahf[mt], bhf[nt] + 2);
                }
            #pragma unroll
            for (int mt = 0; mt < 4; mt++)
                #pragma unroll
                for (int nt = 0; nt < 4; nt++) {
                    mma16816(acc[mt][nt * 2],     alf[mt], bhf[nt]);
                    mma16816(acc[mt][nt * 2 + 1], alf[mt], bhf[nt] + 2);
                }
            #pragma unroll
            for (int mt = 0; mt < 4; mt++)
                #pragma unroll
                for (int nt = 0; nt < 4; nt++) {
                    mma16816(acc[mt][nt * 2],     ahf[mt], blf[nt]);
                    mma16816(acc[mt][nt * 2 + 1], ahf[mt], blf[nt] + 2);
                }
        }
        __syncthreads();
    }

    int qrow = lane >> 2;
    int qcol = (lane & 3) * 2;
    #pragma unroll
    for (int mt = 0; mt < 4; mt++) {
        int m0 = by + wm * 64 + mt * 16 + qrow;
        #pragma unroll
        for (int ntt = 0; ntt < 8; ntt++) {
            int n = bx + wn * 64 + ntt * 8 + qcol;
            float2 bv = *(const float2*)&bias[n];
            float x0 = acc[mt][ntt][0] + bv.x;
            float x1 = acc[mt][ntt][1] + bv.y;
            float x2 = acc[mt][ntt][2] + bv.x;
            float x3 = acc[mt][ntt][3] + bv.y;
            if (SPLIT) {
                uint32_t h0, l0, h1, l1;
                split_pack(x0, x1, h0, l0);
                split_pack(x2, x3, h1, l1);
                *(uint32_t*)&Ch[(size_t)m0 * D_MODEL + n]       = h0;
                *(uint32_t*)&Cl[(size_t)m0 * D_MODEL + n]       = l0;
                *(uint32_t*)&Ch[(size_t)(m0 + 8) * D_MODEL + n] = h1;
                *(uint32_t*)&Cl[(size_t)(m0 + 8) * D_MODEL + n] = l1;
            } else {
                float2 r0 = {x0, x1}, r1 = {x2, x3};
                *(float2*)&C[(size_t)m0 * D_MODEL + n]       = r0;
                *(float2*)&C[(size_t)(m0 + 8) * D_MODEL + n] = r1;
            }
        }
    }
}

// fused QKV: grid.z picks the weight/bias/output triple
__global__ __launch_bounds__(256, 1) void gemm_qkv(
    const __nv_bfloat16* __restrict__ Xh, const __nv_bfloat16* __restrict__ Xl,
    const __nv_bfloat16* __restrict__ Wth, const __nv_bfloat16* __restrict__ Wtl,
    const float* __restrict__ bq, const float* __restrict__ bk, const float* __restrict__ bv,
    __nv_bfloat16* __restrict__ Qh, __nv_bfloat16* __restrict__ Ql,
    __nv_bfloat16* __restrict__ Kh, __nv_bfloat16* __restrict__ Kl,
    __nv_bfloat16* __restrict__ Vh, __nv_bfloat16* __restrict__ Vl)
{
    extern __shared__ __align__(1024) char smc[];
    uint32_t sbase = smem_u32(smc);
    int z = blockIdx.z;
    const size_t WSZ = (size_t)D_MODEL * D_MODEL;
    const __nv_bfloat16* Bh = Wth + (size_t)z * WSZ;
    const __nv_bfloat16* Bl = Wtl + (size_t)z * WSZ;
    const float* bias = (z == 0) ? bq : (z == 1) ? bk : bv;
    __nv_bfloat16* Ch = (z == 0) ? Qh : (z == 1) ? Kh : Vh;
    __nv_bfloat16* Cl = (z == 0) ? Ql : (z == 1) ? Kl : Vl;
    gemm_core<1>(sbase, Xh, Xl, Bh, Bl, bias, nullptr, Ch, Cl,
                 blockIdx.x * 256, blockIdx.y * 128);
}

__global__ __launch_bounds__(256, 1) void gemm_out(
    const __nv_bfloat16* __restrict__ Ah, const __nv_bfloat16* __restrict__ Al,
    const __nv_bfloat16* __restrict__ Bh, const __nv_bfloat16* __restrict__ Bl,
    const float* __restrict__ bias, float* __restrict__ C)
{
    extern __shared__ __align__(1024) char smc[];
    uint32_t sbase = smem_u32(smc);
    gemm_core<0>(sbase, Ah, Al, Bh, Bl, bias, C, nullptr, nullptr,
                 blockIdx.x * 256, blockIdx.y * 128);
}

// ---------------- HMMA flash attention (causal, bf16x3 scores + bf16x3 PV) ----------------
#define ATT_QH   0
#define ATT_QL   32768
#define ATT_STG  65536
#define ATT_STGB 65536
#define ATT_KH   0
#define ATT_KL   16384
#define ATT_VH   32768
#define ATT_VL   49152
#define ATTN_SMEM 196608
#define KSCALE 0.12751744f   // log2(e)/sqrt(128)

__global__ __launch_bounds__(256, 1) void attn_hmma(
    const __nv_bfloat16* __restrict__ Qh, const __nv_bfloat16* __restrict__ Ql,
    const __nv_bfloat16* __restrict__ Kh, const __nv_bfloat16* __restrict__ Kl,
    const __nv_bfloat16* __restrict__ Vh, const __nv_bfloat16* __restrict__ Vl,
    __nv_bfloat16* __restrict__ AVh, __nv_bfloat16* __restrict__ AVl)
{
    extern __shared__ __align__(1024) char sma[];
    uint32_t sbase = smem_u32(sma);
    int tid  = threadIdx.x;
    int wq   = tid >> 5;
    int lane = tid & 31;

    int qt = (int)gridDim.x - 1 - (int)blockIdx.x;  // long CTAs first
    int bh = blockIdx.y;
    int b  = bh >> 4, h = bh & 15;
    int q0c = qt * 128;
    int ntiles = 2 * qt + 2;

    int aq_row = wq * 16 + (lane & 15);
    int aq_csel = (lane >> 4) << 3;
    int bk_row = (lane & 7) + ((lane >> 4) << 3);
    int bk_csel = ((lane >> 3) & 1) << 3;
    int v_row = lane & 15;
    int v_csel = (lane >> 4) << 3;

    {
        #pragma unroll
        for (int j = 0; j < 8; j++) {
            int idx = tid + j * 256;
            int r = idx >> 4, c16 = idx & 15;
            uint32_t soff = (uint32_t)((c16 >> 3) * 16384 + SWZ128(r * 128 + (c16 & 7) * 16));
            size_t goff = (size_t)(b * S_LEN + q0c + r) * D_MODEL + h * D_HEAD + c16 * 8;
            cp_async16(sbase + ATT_QH + soff, Qh + goff);
            cp_async16(sbase + ATT_QL + soff, Ql + goff);
        }
        CP_COMMIT();
    }

    auto issueKV = [&](int kt) {
        int k0 = kt * 64;
        uint32_t sg = sbase + ATT_STG + (kt & 1) * ATT_STGB;
        #pragma unroll
        for (int j = 0; j < 4; j++) {
            int idx = tid + j * 256;
            int r = idx >> 4, c16 = idx & 15;
            uint32_t soff = (uint32_t)((c16 >> 3) * 8192 + SWZ128(r * 128 + (c16 & 7) * 16));
            size_t goff = (size_t)(b * S_LEN + k0 + r) * D_MODEL + h * D_HEAD + c16 * 8;
            cp_async16(sg + ATT_KH + soff, Kh + goff);
            cp_async16(sg + ATT_KL + soff, Kl + goff);
            cp_async16(sg + ATT_VH + soff, Vh + goff);
            cp_async16(sg + ATT_VL + soff, Vl + goff);
        }
        CP_COMMIT();
    };

    issueKV(0);

    float acco[16][4];
    #pragma unroll
    for (int i = 0; i < 16; i++)
        #pragma unroll
        for (int j = 0; j < 4; j++) acco[i][j] = 0.f;
    float m0 = -1e30f, m1 = -1e30f, l0 = 0.f, l1 = 0.f;

    int qcol = (lane & 3) << 1;
    int qg0 = q0c + wq * 16 + (lane >> 2);

    for (int kt = 0; kt < ntiles; kt++) {
        if (kt + 1 < ntiles) issueKV(kt + 1);
        if (kt + 1 < ntiles) { CP_WAIT1(); } else { CP_WAIT0(); }
        __syncthreads();

        uint32_t sg = sbase + ATT_STG + (kt & 1) * ATT_STGB;
        int k0 = kt * 64;

        float accs[8][4];
        #pragma unroll
        for (int i = 0; i < 8; i++)
            #pragma unroll
            for (int j = 0; j < 4; j++) accs[i][j] = 0.f;

        #pragma unroll
        for (int ks = 0; ks < 8; ks++) {
            int qc = ks * 16 + aq_csel;
            uint32_t qoff = (uint32_t)((qc >> 6) * 16384 + SWZ128(aq_row * 128 + (qc & 63) * 2));
            uint32_t aqh[4], aql[4], bk[4][4];
            ldmx4(aqh, sbase + ATT_QH + qoff);
            ldmx4(aql, sbase + ATT_QL + qoff);
            int kc = ks * 16 + bk_csel;
            uint32_t kcoff = (uint32_t)((kc >> 6) * 8192);
            #pragma unroll
            for (int ntp = 0; ntp < 4; ntp++)
                ldmx4(bk[ntp], sg + ATT_KH + kcoff + SWZ128((ntp * 16 + bk_row) * 128 + (kc & 63) * 2));
            #pragma unroll
            for (int ntp = 0; ntp < 4; ntp++) {
                mma16816(accs[ntp * 2],     aqh, bk[ntp]);
                mma16816(accs[ntp * 2 + 1], aqh, bk[ntp] + 2);
            }
            #pragma unroll
            for (int ntp = 0; ntp < 4; ntp++) {
                mma16816(accs[ntp * 2],     aql, bk[ntp]);
                mma16816(accs[ntp * 2 + 1], aql, bk[ntp] + 2);
            }
            #pragma unroll
            for (int ntp = 0; ntp < 4; ntp++)
                ldmx4(bk[ntp], sg + ATT_KL + kcoff + SWZ128((ntp * 16 + bk_row) * 128 + (kc & 63) * 2));
            #pragma unroll
            for (int ntp = 0; ntp < 4; ntp++) {
                mma16816(accs[ntp * 2],     aqh, bk[ntp]);
                mma16816(accs[ntp * 2 + 1], aqh, bk[ntp] + 2);
            }
        }

        bool masked = (k0 + 63 > q0c);
        #pragma unroll
        for (int nt = 0; nt < 8; nt++) {
            #pragma unroll
            for (int j = 0; j < 4; j++) accs[nt][j] *= KSCALE;
            if (masked) {
                int kg = k0 + nt * 8 + qcol;
                if (kg     > qg0)     accs[nt][0] = -3e38f;
                if (kg + 1 > qg0)     accs[nt][1] = -3e38f;
                if (kg     > qg0 + 8) accs[nt][2] = -3e38f;
                if (kg + 1 > qg0 + 8) accs[nt][3] = -3e38f;
            }
        }

        float t0 = -3e38f, t1 = -3e38f;
        #pragma unroll
        for (int nt = 0; nt < 8; nt++) {
            t0 = fmaxf(t0, fmaxf(accs[nt][0], accs[nt][1]));
            t1 = fmaxf(t1, fmaxf(accs[nt][2], accs[nt][3]));
        }
        t0 = fmaxf(t0, __shfl_xor_sync(0xffffffffu, t0, 1));
        t0 = fmaxf(t0, __shfl_xor_sync(0xffffffffu, t0, 2));
        t1 = fmaxf(t1, __shfl_xor_sync(0xffffffffu, t1, 1));
        t1 = fmaxf(t1, __shfl_xor_sync(0xffffffffu, t1, 2));
        float mn0 = fmaxf(m0, t0), mn1 = fmaxf(m1, t1);
        float c0 = ex2f(m0 - mn0), c1 = ex2f(m1 - mn1);
        m0 = mn0; m1 = mn1;

        float s0 = 0.f, s1 = 0.f;
        #pragma unroll
        for (int nt = 0; nt < 8; nt++) {
            accs[nt][0] = ex2f(accs[nt][0] - mn0);
            accs[nt][1] = ex2f(accs[nt][1] - mn0);
            accs[nt][2] = ex2f(accs[nt][2] - mn1);
            accs[nt][3] = ex2f(accs[nt][3] - mn1);
            s0 += accs[nt][0] + accs[nt][1];
            s1 += accs[nt][2] + accs[nt][3];
        }
        s0 += __shfl_xor_sync(0xffffffffu, s0, 1);
        s0 += __shfl_xor_sync(0xffffffffu, s0, 2);
        s1 += __shfl_xor_sync(0xffffffffu, s1, 1);
        s1 += __shfl_xor_sync(0xffffffffu, s1, 2);
        l0 = l0 * c0 + s0;
        l1 = l1 * c1 + s1;

        #pragma unroll
        for (int nt = 0; nt < 16; nt++) {
            acco[nt][0] *= c0; acco[nt][1] *= c0;
            acco[nt][2] *= c1; acco[nt][3] *= c1;
        }

        #pragma unroll
        for (int kk = 0; kk < 4; kk++) {
            uint32_t ph[4], pl[4];
            split_pack(accs[2*kk][0],   accs[2*kk][1],   ph[0], pl[0]);
            split_pack(accs[2*kk][2],   accs[2*kk][3],   ph[1], pl[1]);
            split_pack(accs[2*kk+1][0], accs[2*kk+1][1], ph[2], pl[2]);
            split_pack(accs[2*kk+1][2], accs[2*kk+1][3], ph[3], pl[3]);
            int vr = kk * 16 + v_row;
            #pragma unroll
            for (int np = 0; np < 8; np++) {
                int n0 = np * 16 + v_csel;
                uint32_t voff = (uint32_t)((n0 >> 6) * 8192 + SWZ128(vr * 128 + (n0 & 63) * 2));
                uint32_t vf[4];
                ldmx4t(vf, sg + ATT_VH + voff);
                mma16816(acco[np * 2],     ph, vf);
                mma16816(acco[np * 2 + 1], ph, vf + 2);
                mma16816(acco[np * 2],     pl, vf);
                mma16816(acco[np * 2 + 1], pl, vf + 2);
            }
            #pragma unroll
            for (int np = 0; np < 8; np++) {
                int n0 = np * 16 + v_csel;
                uint32_t voff = (uint32_t)((n0 >> 6) * 8192 + SWZ128(vr * 128 + (n0 & 63) * 2));
                uint32_t vf[4];
                ldmx4t(vf, sg + ATT_VL + voff);
                mma16816(acco[np * 2],     ph, vf);
                mma16816(acco[np * 2 + 1], ph, vf + 2);
            }
        }
        __syncthreads();
    }

    float inv0 = 1.f / l0, inv1 = 1.f / l1;
    size_t row0 = (size_t)(b * S_LEN + qg0) * D_MODEL + h * D_HEAD;
    size_t row1 = row0 + 8 * D_MODEL;
    #pragma unroll
    for (int nt = 0; nt < 16; nt++) {
        int n = nt * 8 + qcol;
        uint32_t h0, lo0, h1, lo1;
        split_pack(acco[nt][0] * inv0, acco[nt][1] * inv0, h0, lo0);
        split_pack(acco[nt][2] * inv1, acco[nt][3] * inv1, h1, lo1);
        *(uint32_t*)&AVh[row0 + n] = h0;
        *(uint32_t*)&AVl[row0 + n] = lo0;
        *(uint32_t*)&AVh[row1 + n] = h1;
        *(uint32_t*)&AVl[row1 + n] = lo1;
    }
}

// ---------------- launch ----------------
extern "C" void kernel_launch(void* const* d_in, const int* in_sizes, int n_in,
                              void* d_out, int out_size)
{
    const float* X    = (const float*)d_in[0];
    const float* ln_g = (const float*)d_in[1];
    const float* ln_b = (const float*)d_in[2];
    const float* Wq   = (const float*)d_in[3];
    const float* bq   = (const float*)d_in[4];
    const float* Wk   = (const float*)d_in[5];
    const float* bk   = (const float*)d_in[6];
    const float* Wv   = (const float*)d_in[7];
    const float* bv   = (const float*)d_in[8];
    const float* Wo   = (const float*)d_in[9];
    const float* bo   = (const float*)d_in[10];
    float* out = (float*)d_out;

    __nv_bfloat16 *Xh, *Xl, *Qh, *Ql, *Kh, *Kl, *Vh, *Vl, *AVh, *AVl, *Wth, *Wtl;
    cudaGetSymbolAddress((void**)&Xh,  g_Xh);
    cudaGetSymbolAddress((void**)&Xl,  g_Xl);
    cudaGetSymbolAddress((void**)&Qh,  g_Qh);
    cudaGetSymbolAddress((void**)&Ql,  g_Ql);
    cudaGetSymbolAddress((void**)&Kh,  g_Kh);
    cudaGetSymbolAddress((void**)&Kl,  g_Kl);
    cudaGetSymbolAddress((void**)&Vh,  g_Vh);
    cudaGetSymbolAddress((void**)&Vl,  g_Vl);
    cudaGetSymbolAddress((void**)&AVh, g_AVh);
    cudaGetSymbolAddress((void**)&AVl, g_AVl);
    cudaGetSymbolAddress((void**)&Wth, g_Wth);
    cudaGetSymbolAddress((void**)&Wtl, g_Wtl);

    const size_t WSZ = (size_t)D_MODEL * D_MODEL;

    dim3 tg(D_MODEL / 32, D_MODEL / 32, 4);
    transpose_split_kernel<<<tg, 256>>>(Wq, Wk, Wv, Wo, Wth, Wtl);

    ln_split_kernel<<<NROWS, 256>>>(X, ln_g, ln_b, Xh, Xl);

    cudaFuncSetAttribute(gemm_qkv, cudaFuncAttributeMaxDynamicSharedMemorySize, GEMM_SMEM);
    cudaFuncSetAttribute(gemm_out, cudaFuncAttributeMaxDynamicSharedMemorySize, GEMM_SMEM);
    dim3 gq(D_MODEL / 256, NROWS / 128, 3);
    gemm_qkv<<<gq, 256, GEMM_SMEM>>>(Xh, Xl, Wth, Wtl, bq, bk, bv,
                                     Qh, Ql, Kh, Kl, Vh, Vl);

    cudaFuncSetAttribute(attn_hmma, cudaFuncAttributeMaxDynamicSharedMemorySize, ATTN_SMEM);
    attn_hmma<<<dim3(S_LEN / 128, BATCH * N_HEADS), 256, ATTN_SMEM>>>(
        Qh, Ql, Kh, Kl, Vh, Vl, AVh, AVl);

    dim3 gg(D_MODEL / 256, NROWS / 128);
    gemm_out<<<gg, 256, GEMM_SMEM>>>(AVh, AVl, Wth + 3 * WSZ, Wtl + 3 * WSZ, bo, out);
}

// round 17
// speedup vs baseline: 1.0915x; 1.0915x over previous
#include <cuda_runtime.h>
#include <cuda_bf16.h>
#include <math.h>
#include <cstdint>

#define D_MODEL 2048
#define S_LEN   2048
#define BATCH   2
#define NROWS   (BATCH * S_LEN)   // 4096
#define N_HEADS 16
#define D_HEAD  128

// ---------------- scratch (alloc-free rule: __device__ globals) ----------------
__device__ __nv_bfloat16 g_Xh [(size_t)NROWS * D_MODEL];
__device__ __nv_bfloat16 g_Xl [(size_t)NROWS * D_MODEL];
__device__ __nv_bfloat16 g_Qh [(size_t)NROWS * D_MODEL];
__device__ __nv_bfloat16 g_Ql [(size_t)NROWS * D_MODEL];
__device__ __nv_bfloat16 g_Kh [(size_t)NROWS * D_MODEL];
__device__ __nv_bfloat16 g_Kl [(size_t)NROWS * D_MODEL];
__device__ __nv_bfloat16 g_Vh [(size_t)NROWS * D_MODEL];
__device__ __nv_bfloat16 g_Vl [(size_t)NROWS * D_MODEL];
__device__ __nv_bfloat16 g_AVh[(size_t)NROWS * D_MODEL];
__device__ __nv_bfloat16 g_AVl[(size_t)NROWS * D_MODEL];
// transposed weight splits: [4][N=2048][K=2048], order: Wq, Wk, Wv, Wo
__device__ __nv_bfloat16 g_Wth[(size_t)4 * D_MODEL * D_MODEL];
__device__ __nv_bfloat16 g_Wtl[(size_t)4 * D_MODEL * D_MODEL];

// ---------------- PTX helpers (valid on plain sm_103 target) ----------------
__device__ __forceinline__ uint32_t smem_u32(const void* p) {
    uint32_t a;
    asm("{ .reg .u64 t; cvta.to.shared.u64 t, %1; cvt.u32.u64 %0, t; }" : "=r"(a) : "l"(p));
    return a;
}
#define SWZ128(off) ((off) ^ (((off) >> 3) & 0x70))
#define SWZ64(off)  ((off) ^ (((off) >> 3) & 0x30))

__device__ __forceinline__ void cp_async16(uint32_t saddr, const void* gaddr) {
    asm volatile("cp.async.cg.shared.global [%0], [%1], 16;\n" :: "r"(saddr), "l"(gaddr));
}
#define CP_COMMIT() asm volatile("cp.async.commit_group;\n" ::: "memory")
#define CP_WAIT0()  asm volatile("cp.async.wait_group 0;\n" ::: "memory")
#define CP_WAIT1()  asm volatile("cp.async.wait_group 1;\n" ::: "memory")

__device__ __forceinline__ void ldmx4(uint32_t* r, uint32_t addr) {
    asm volatile("ldmatrix.sync.aligned.m8n8.x4.shared.b16 {%0,%1,%2,%3}, [%4];"
        : "=r"(r[0]), "=r"(r[1]), "=r"(r[2]), "=r"(r[3]) : "r"(addr));
}
__device__ __forceinline__ void ldmx4t(uint32_t* r, uint32_t addr) {
    asm volatile("ldmatrix.sync.aligned.m8n8.x4.trans.shared.b16 {%0,%1,%2,%3}, [%4];"
        : "=r"(r[0]), "=r"(r[1]), "=r"(r[2]), "=r"(r[3]) : "r"(addr));
}
// non-volatile — pure register op, lets ptxas interleave independent MMAs.
__device__ __forceinline__ void mma16816(float* d, const uint32_t* a, const uint32_t* b) {
    asm("mma.sync.aligned.m16n8k16.row.col.f32.bf16.bf16.f32 "
        "{%0,%1,%2,%3}, {%4,%5,%6,%7}, {%8,%9}, {%0,%1,%2,%3};"
        : "+f"(d[0]), "+f"(d[1]), "+f"(d[2]), "+f"(d[3])
        : "r"(a[0]), "r"(a[1]), "r"(a[2]), "r"(a[3]), "r"(b[0]), "r"(b[1]));
}
__device__ __forceinline__ float ex2f(float x) {
    float y;
    asm("ex2.approx.f32 %0, %1;" : "=f"(y) : "f"(x));
    return y;
}
__device__ __forceinline__ void split_pack(float a, float b, uint32_t& h, uint32_t& l) {
    __nv_bfloat16 ha = __float2bfloat16(a), hb = __float2bfloat16(b);
    __nv_bfloat162 th, tl;
    th.x = ha; th.y = hb;
    tl.x = __float2bfloat16(a - __bfloat162float(ha));
    tl.y = __float2bfloat16(b - __bfloat162float(hb));
    h = *(uint32_t*)&th;
    l = *(uint32_t*)&tl;
}

// ---------------- LayerNorm + bf16 split: one block per row ----------------
__global__ __launch_bounds__(256) void ln_split_kernel(
    const float* __restrict__ X, const float* __restrict__ gam,
    const float* __restrict__ bet, __nv_bfloat16* __restrict__ Xh,
    __nv_bfloat16* __restrict__ Xl)
{
    int row = blockIdx.x;
    const float4* x4 = (const float4*)(X + (size_t)row * D_MODEL);
    const float4* g4 = (const float4*)gam;
    const float4* b4 = (const float4*)bet;
    int tid = threadIdx.x;

    float4 v0 = x4[tid];
    float4 v1 = x4[tid + 256];
    float s  = v0.x + v0.y + v0.z + v0.w + v1.x + v1.y + v1.z + v1.w;
    float ss = v0.x*v0.x + v0.y*v0.y + v0.z*v0.z + v0.w*v0.w
             + v1.x*v1.x + v1.y*v1.y + v1.z*v1.z + v1.w*v1.w;

    #pragma unroll
    for (int off = 16; off; off >>= 1) {
        s  += __shfl_xor_sync(0xffffffffu, s,  off);
        ss += __shfl_xor_sync(0xffffffffu, ss, off);
    }
    __shared__ float rs[8], rss[8];
    __shared__ float s_mean, s_rstd;
    int w = tid >> 5, l = tid & 31;
    if (l == 0) { rs[w] = s; rss[w] = ss; }
    __syncthreads();
    if (tid == 0) {
        float t = 0.f, tt = 0.f;
        #pragma unroll
        for (int i = 0; i < 8; i++) { t += rs[i]; tt += rss[i]; }
        float mean = t * (1.f / D_MODEL);
        float var  = tt * (1.f / D_MODEL) - mean * mean;
        s_mean = mean;
        s_rstd = rsqrtf(var + 1e-5f);
    }
    __syncthreads();
    float mean = s_mean, rstd = s_rstd;

    float4 g0 = g4[tid], g1 = g4[tid + 256];
    float4 c0 = b4[tid], c1 = b4[tid + 256];
    float r[8];
    r[0] = (v0.x - mean) * rstd * g0.x + c0.x;
    r[1] = (v0.y - mean) * rstd * g0.y + c0.y;
    r[2] = (v0.z - mean) * rstd * g0.z + c0.z;
    r[3] = (v0.w - mean) * rstd * g0.w + c0.w;
    r[4] = (v1.x - mean) * rstd * g1.x + c1.x;
    r[5] = (v1.y - mean) * rstd * g1.y + c1.y;
    r[6] = (v1.z - mean) * rstd * g1.z + c1.z;
    r[7] = (v1.w - mean) * rstd * g1.w + c1.w;

    uint32_t h0, l0, h1, l1, h2, l2, h3, l3;
    split_pack(r[0], r[1], h0, l0);
    split_pack(r[2], r[3], h1, l1);
    split_pack(r[4], r[5], h2, l2);
    split_pack(r[6], r[7], h3, l3);
    size_t base = (size_t)row * D_MODEL;
    uint2 vh0 = {h0, h1}, vl0 = {l0, l1}, vh1 = {h2, h3}, vl1 = {l2, l3};
    *(uint2*)(Xh + base + tid * 4)         = vh0;
    *(uint2*)(Xh + base + (tid + 256) * 4) = vh1;
    *(uint2*)(Xl + base + tid * 4)         = vl0;
    *(uint2*)(Xl + base + (tid + 256) * 4) = vl1;
}

// ---------------- weight transpose + split (all 4 weights, grid.z selects) ----------------
__global__ __launch_bounds__(256) void transpose_split_kernel(
    const float* __restrict__ W0, const float* __restrict__ W1,
    const float* __restrict__ W2, const float* __restrict__ W3,
    __nv_bfloat16* __restrict__ Th, __nv_bfloat16* __restrict__ Tl)
{
    __shared__ float t[32][33];
    int wsel = blockIdx.z;
    const float* W = (wsel == 0) ? W0 : (wsel == 1) ? W1 : (wsel == 2) ? W2 : W3;
    size_t obase = (size_t)wsel * D_MODEL * D_MODEL;
    int bx = blockIdx.x * 32;   // n0
    int by = blockIdx.y * 32;   // k0
    int tx = threadIdx.x & 31, ty = threadIdx.x >> 5;
    #pragma unroll
    for (int r = 0; r < 4; r++)
        t[ty + r * 8][tx] = W[(size_t)(by + ty + r * 8) * D_MODEL + bx + tx];
    __syncthreads();
    #pragma unroll
    for (int r = 0; r < 4; r++) {
        float v = t[tx][ty + r * 8];
        __nv_bfloat16 h = __float2bfloat16(v);
        size_t idx = obase + (size_t)(bx + ty + r * 8) * D_MODEL + by + tx;
        Th[idx] = h;
        Tl[idx] = __float2bfloat16(v - __bfloat162float(h));
    }
}

// ---------------- HMMA bf16x3 GEMM core (BK=32, SW64, 2 CTAs/SM, lookahead-1, 1 sync/iter) ----------------
#define TILE_B 8192                        // 128 rows x 32 K bf16 = 8KB (64B rows)
#define GDEPTH 3
#define STAGE_BYTES (4 * TILE_B)           // 32KB: Ah|Al|Bh|Bl
#define GEMM_SMEM (GDEPTH * STAGE_BYTES)   // 96KB -> 2 CTAs/SM
#define NKITER 64                          // 2048 / 32

template <int SPLIT>
__device__ __forceinline__ void gemm_core(
    uint32_t sbase,
    const __nv_bfloat16* Ah, const __nv_bfloat16* Al,
    const __nv_bfloat16* Bh, const __nv_bfloat16* Bl,
    const float* bias, float* C,
    __nv_bfloat16* Ch, __nv_bfloat16* Cl,
    int bx, int by)
{
    int tid  = threadIdx.x;
    int wid  = tid >> 5;
    int lane = tid & 31;
    int wm = wid & 1;
    int wn = wid >> 1;

    float acc[4][4][4];
    #pragma unroll
    for (int i = 0; i < 4; i++)
        #pragma unroll
        for (int j = 0; j < 4; j++)
            #pragma unroll
            for (int k = 0; k < 4; k++) acc[i][j][k] = 0.f;

    int lr = lane & 7, g = lane >> 3;
    int a_row = wm * 64 + ((g & 1) << 3) + lr;
    int a_col = (g >> 1) << 4;
    int b_row = wn * 32 + ((g >> 1) << 3) + lr;
    int b_col = (g & 1) << 4;

    auto issue = [&](int it) {
        int k0 = it * 32;
        int s  = it % GDEPTH;
        uint32_t sa = sbase + s * STAGE_BYTES;
        #pragma unroll
        for (int j = 0; j < 2; j++) {
            int c = tid + j * 256;            // 0..511
            int r = c >> 2, c16 = c & 3;      // tile row, 16B chunk in 64B row
            uint32_t off = SWZ64((uint32_t)(r * 64 + c16 * 16));
            size_t aoff = (size_t)(by + r) * D_MODEL + k0 + c16 * 8;
            size_t boff = (size_t)(bx + r) * D_MODEL + k0 + c16 * 8;
            cp_async16(sa + off,              Ah + aoff);
            cp_async16(sa + TILE_B + off,     Al + aoff);
            cp_async16(sa + 2 * TILE_B + off, Bh + boff);
            cp_async16(sa + 3 * TILE_B + off, Bl + boff);
        }
        CP_COMMIT();
    };

    issue(0);

    for (int i = 0; i < NKITER; i++) {
        CP_WAIT0();
        __syncthreads();
        // lookahead-1: stage (i+1)%3 is distinct from every possible reader
        // (i%3 current, (i-1)%3 just-finished) -> no trailing sync needed.
        if (i + 1 < NKITER) issue(i + 1);

        int s = i % GDEPTH;
        uint32_t sa = sbase + s * STAGE_BYTES;

        #pragma unroll
        for (int ks = 0; ks < 2; ks++) {
            uint32_t ahf[4][4], alf[4][4], bhf[2][4], blf[2][4];
            #pragma unroll
            for (int mt = 0; mt < 4; mt++) {
                uint32_t off = SWZ64((uint32_t)((a_row + mt * 16) * 64 + ks * 32 + a_col));
                ldmx4(ahf[mt], sa + off);
                ldmx4(alf[mt], sa + TILE_B + off);
            }
            #pragma unroll
            for (int nt = 0; nt < 2; nt++) {
                uint32_t off = SWZ64((uint32_t)((b_row + nt * 16) * 64 + ks * 32 + b_col));
                ldmx4(bhf[nt], sa + 2 * TILE_B + off);
                ldmx4(blf[nt], sa + 3 * TILE_B + off);
            }
            // three sweeps: consecutive MMAs never share an accumulator
            #pragma unroll
            for (int mt = 0; mt < 4; mt++)
                #pragma unroll
                for (int nt = 0; nt < 2; nt++) {
                    mma16816(acc[mt][nt * 2],     ahf[mt], bhf[nt]);
                    mma16816(acc[mt][nt * 2 + 1], ahf[mt], bhf[nt] + 2);
                }
            #pragma unroll
            for (int mt = 0; mt < 4; mt++)
                #pragma unroll
                for (int nt = 0; nt < 2; nt++) {
                    mma16816(acc[mt][nt * 2],     alf[mt], bhf[nt]);
                    mma16816(acc[mt][nt * 2 + 1], alf[mt], bhf[nt] + 2);
                }
            #pragma unroll
            for (int mt = 0; mt < 4; mt++)
                #pragma unroll
                for (int nt = 0; nt < 2; nt++) {
                    mma16816(acc[mt][nt * 2],     ahf[mt], blf[nt]);
                    mma16816(acc[mt][nt * 2 + 1], ahf[mt], blf[nt] + 2);
                }
        }
    }

    int qrow = lane >> 2;
    int qcol = (lane & 3) * 2;
    #pragma unroll
    for (int mt = 0; mt < 4; mt++) {
        int m0 = by + wm * 64 + mt * 16 + qrow;
        #pragma unroll
        for (int ntt = 0; ntt < 4; ntt++) {
            int n = bx + wn * 32 + ntt * 8 + qcol;
            float2 bv = *(const float2*)&bias[n];
            float x0 = acc[mt][ntt][0] + bv.x;
            float x1 = acc[mt][ntt][1] + bv.y;
            float x2 = acc[mt][ntt][2] + bv.x;
            float x3 = acc[mt][ntt][3] + bv.y;
            if (SPLIT) {
                uint32_t h0, l0, h1, l1;
                split_pack(x0, x1, h0, l0);
                split_pack(x2, x3, h1, l1);
                *(uint32_t*)&Ch[(size_t)m0 * D_MODEL + n]       = h0;
                *(uint32_t*)&Cl[(size_t)m0 * D_MODEL + n]       = l0;
                *(uint32_t*)&Ch[(size_t)(m0 + 8) * D_MODEL + n] = h1;
                *(uint32_t*)&Cl[(size_t)(m0 + 8) * D_MODEL + n] = l1;
            } else {
                float2 r0 = {x0, x1}, r1 = {x2, x3};
                *(float2*)&C[(size_t)m0 * D_MODEL + n]       = r0;
                *(float2*)&C[(size_t)(m0 + 8) * D_MODEL + n] = r1;
            }
        }
    }
}

// fused QKV: grid.z picks the weight/bias/output triple
__global__ __launch_bounds__(256, 2) void gemm_qkv(
    const __nv_bfloat16* __restrict__ Xh, const __nv_bfloat16* __restrict__ Xl,
    const __nv_bfloat16* __restrict__ Wth, const __nv_bfloat16* __restrict__ Wtl,
    const float* __restrict__ bq, const float* __restrict__ bk, const float* __restrict__ bv,
    __nv_bfloat16* __restrict__ Qh, __nv_bfloat16* __restrict__ Ql,
    __nv_bfloat16* __restrict__ Kh, __nv_bfloat16* __restrict__ Kl,
    __nv_bfloat16* __restrict__ Vh, __nv_bfloat16* __restrict__ Vl)
{
    extern __shared__ __align__(1024) char smc[];
    uint32_t sbase = smem_u32(smc);
    int z = blockIdx.z;
    const size_t WSZ = (size_t)D_MODEL * D_MODEL;
    const __nv_bfloat16* Bh = Wth + (size_t)z * WSZ;
    const __nv_bfloat16* Bl = Wtl + (size_t)z * WSZ;
    const float* bias = (z == 0) ? bq : (z == 1) ? bk : bv;
    __nv_bfloat16* Ch = (z == 0) ? Qh : (z == 1) ? Kh : Vh;
    __nv_bfloat16* Cl = (z == 0) ? Ql : (z == 1) ? Kl : Vl;
    gemm_core<1>(sbase, Xh, Xl, Bh, Bl, bias, nullptr, Ch, Cl,
                 blockIdx.x * 128, blockIdx.y * 128);
}

__global__ __launch_bounds__(256, 2) void gemm_out(
    const __nv_bfloat16* __restrict__ Ah, const __nv_bfloat16* __restrict__ Al,
    const __nv_bfloat16* __restrict__ Bh, const __nv_bfloat16* __restrict__ Bl,
    const float* __restrict__ bias, float* __restrict__ C)
{
    extern __shared__ __align__(1024) char smc[];
    uint32_t sbase = smem_u32(smc);
    gemm_core<0>(sbase, Ah, Al, Bh, Bl, bias, C, nullptr, nullptr,
                 blockIdx.x * 128, blockIdx.y * 128);
}

// ---------------- HMMA flash attention (causal, bf16x3 scores + bf16x3 PV) ----------------
#define ATT_QH   0
#define ATT_QL   32768
#define ATT_STG  65536
#define ATT_STGB 65536
#define ATT_KH   0
#define ATT_KL   16384
#define ATT_VH   32768
#define ATT_VL   49152
#define ATTN_SMEM 196608
#define KSCALE 0.12751744f   // log2(e)/sqrt(128)

__global__ __launch_bounds__(256, 1) void attn_hmma(
    const __nv_bfloat16* __restrict__ Qh, const __nv_bfloat16* __restrict__ Ql,
    const __nv_bfloat16* __restrict__ Kh, const __nv_bfloat16* __restrict__ Kl,
    const __nv_bfloat16* __restrict__ Vh, const __nv_bfloat16* __restrict__ Vl,
    __nv_bfloat16* __restrict__ AVh, __nv_bfloat16* __restrict__ AVl)
{
    extern __shared__ __align__(1024) char sma[];
    uint32_t sbase = smem_u32(sma);
    int tid  = threadIdx.x;
    int wq   = tid >> 5;
    int lane = tid & 31;

    int qt = (int)gridDim.x - 1 - (int)blockIdx.x;  // long CTAs first
    int bh = blockIdx.y;
    int b  = bh >> 4, h = bh & 15;
    int q0c = qt * 128;
    int ntiles = 2 * qt + 2;

    int aq_row = wq * 16 + (lane & 15);
    int aq_csel = (lane >> 4) << 3;
    int bk_row = (lane & 7) + ((lane >> 4) << 3);
    int bk_csel = ((lane >> 3) & 1) << 3;
    int v_row = lane & 15;
    int v_csel = (lane >> 4) << 3;

    {
        #pragma unroll
        for (int j = 0; j < 8; j++) {
            int idx = tid + j * 256;
            int r = idx >> 4, c16 = idx & 15;
            uint32_t soff = (uint32_t)((c16 >> 3) * 16384 + SWZ128(r * 128 + (c16 & 7) * 16));
            size_t goff = (size_t)(b * S_LEN + q0c + r) * D_MODEL + h * D_HEAD + c16 * 8;
            cp_async16(sbase + ATT_QH + soff, Qh + goff);
            cp_async16(sbase + ATT_QL + soff, Ql + goff);
        }
        CP_COMMIT();
    }

    auto issueKV = [&](int kt) {
        int k0 = kt * 64;
        uint32_t sg = sbase + ATT_STG + (kt & 1) * ATT_STGB;
        #pragma unroll
        for (int j = 0; j < 4; j++) {
            int idx = tid + j * 256;
            int r = idx >> 4, c16 = idx & 15;
            uint32_t soff = (uint32_t)((c16 >> 3) * 8192 + SWZ128(r * 128 + (c16 & 7) * 16));
            size_t goff = (size_t)(b * S_LEN + k0 + r) * D_MODEL + h * D_HEAD + c16 * 8;
            cp_async16(sg + ATT_KH + soff, Kh + goff);
            cp_async16(sg + ATT_KL + soff, Kl + goff);
            cp_async16(sg + ATT_VH + soff, Vh + goff);
            cp_async16(sg + ATT_VL + soff, Vl + goff);
        }
        CP_COMMIT();
    };

    issueKV(0);

    float acco[16][4];
    #pragma unroll
    for (int i = 0; i < 16; i++)
        #pragma unroll
        for (int j = 0; j < 4; j++) acco[i][j] = 0.f;
    float m0 = -1e30f, m1 = -1e30f, l0 = 0.f, l1 = 0.f;

    int qcol = (lane & 3) << 1;
    int qg0 = q0c + wq * 16 + (lane >> 2);

    for (int kt = 0; kt < ntiles; kt++) {
        if (kt + 1 < ntiles) issueKV(kt + 1);
        if (kt + 1 < ntiles) { CP_WAIT1(); } else { CP_WAIT0(); }
        __syncthreads();

        uint32_t sg = sbase + ATT_STG + (kt & 1) * ATT_STGB;
        int k0 = kt * 64;

        float accs[8][4];
        #pragma unroll
        for (int i = 0; i < 8; i++)
            #pragma unroll
            for (int j = 0; j < 4; j++) accs[i][j] = 0.f;

        #pragma unroll
        for (int ks = 0; ks < 8; ks++) {
            int qc = ks * 16 + aq_csel;
            uint32_t qoff = (uint32_t)((qc >> 6) * 16384 + SWZ128(aq_row * 128 + (qc & 63) * 2));
            uint32_t aqh[4], aql[4], bk[4][4];
            ldmx4(aqh, sbase + ATT_QH + qoff);
            ldmx4(aql, sbase + ATT_QL + qoff);
            int kc = ks * 16 + bk_csel;
            uint32_t kcoff = (uint32_t)((kc >> 6) * 8192);
            #pragma unroll
            for (int ntp = 0; ntp < 4; ntp++)
                ldmx4(bk[ntp], sg + ATT_KH + kcoff + SWZ128((ntp * 16 + bk_row) * 128 + (kc & 63) * 2));
            #pragma unroll
            for (int ntp = 0; ntp < 4; ntp++) {
                mma16816(accs[ntp * 2],     aqh, bk[ntp]);
                mma16816(accs[ntp * 2 + 1], aqh, bk[ntp] + 2);
            }
            #pragma unroll
            for (int ntp = 0; ntp < 4; ntp++) {
                mma16816(accs[ntp * 2],     aql, bk[ntp]);
                mma16816(accs[ntp * 2 + 1], aql, bk[ntp] + 2);
            }
            #pragma unroll
            for (int ntp = 0; ntp < 4; ntp++)
                ldmx4(bk[ntp], sg + ATT_KL + kcoff + SWZ128((ntp * 16 + bk_row) * 128 + (kc & 63) * 2));
            #pragma unroll
            for (int ntp = 0; ntp < 4; ntp++) {
                mma16816(accs[ntp * 2],     aqh, bk[ntp]);
                mma16816(accs[ntp * 2 + 1], aqh, bk[ntp] + 2);
            }
        }

        bool masked = (k0 + 63 > q0c);
        #pragma unroll
        for (int nt = 0; nt < 8; nt++) {
            #pragma unroll
            for (int j = 0; j < 4; j++) accs[nt][j] *= KSCALE;
            if (masked) {
                int kg = k0 + nt * 8 + qcol;
                if (kg     > qg0)     accs[nt][0] = -3e38f;
                if (kg + 1 > qg0)     accs[nt][1] = -3e38f;
                if (kg     > qg0 + 8) accs[nt][2] = -3e38f;
                if (kg + 1 > qg0 + 8) accs[nt][3] = -3e38f;
            }
        }

        float t0 = -3e38f, t1 = -3e38f;
        #pragma unroll
        for (int nt = 0; nt < 8; nt++) {
            t0 = fmaxf(t0, fmaxf(accs[nt][0], accs[nt][1]));
            t1 = fmaxf(t1, fmaxf(accs[nt][2], accs[nt][3]));
        }
        t0 = fmaxf(t0, __shfl_xor_sync(0xffffffffu, t0, 1));
        t0 = fmaxf(t0, __shfl_xor_sync(0xffffffffu, t0, 2));
        t1 = fmaxf(t1, __shfl_xor_sync(0xffffffffu, t1, 1));
        t1 = fmaxf(t1, __shfl_xor_sync(0xffffffffu, t1, 2));
        float mn0 = fmaxf(m0, t0), mn1 = fmaxf(m1, t1);
        float c0 = ex2f(m0 - mn0), c1 = ex2f(m1 - mn1);
        m0 = mn0; m1 = mn1;

        float s0 = 0.f, s1 = 0.f;
        #pragma unroll
        for (int nt = 0; nt < 8; nt++) {
            accs[nt][0] = ex2f(accs[nt][0] - mn0);
            accs[nt][1] = ex2f(accs[nt][1] - mn0);
            accs[nt][2] = ex2f(accs[nt][2] - mn1);
            accs[nt][3] = ex2f(accs[nt][3] - mn1);
            s0 += accs[nt][0] + accs[nt][1];
            s1 += accs[nt][2] + accs[nt][3];
        }
        s0 += __shfl_xor_sync(0xffffffffu, s0, 1);
        s0 += __shfl_xor_sync(0xffffffffu, s0, 2);
        s1 += __shfl_xor_sync(0xffffffffu, s1, 1);
        s1 += __shfl_xor_sync(0xffffffffu, s1, 2);
        l0 = l0 * c0 + s0;
        l1 = l1 * c1 + s1;

        #pragma unroll
        for (int nt = 0; nt < 16; nt++) {
            acco[nt][0] *= c0; acco[nt][1] *= c0;
            acco[nt][2] *= c1; acco[nt][3] *= c1;
        }

        #pragma unroll
        for (int kk = 0; kk < 4; kk++) {
            uint32_t ph[4], pl[4];
            split_pack(accs[2*kk][0],   accs[2*kk][1],   ph[0], pl[0]);
            split_pack(accs[2*kk][2],   accs[2*kk][3],   ph[1], pl[1]);
            split_pack(accs[2*kk+1][0], accs[2*kk+1][1], ph[2], pl[2]);
            split_pack(accs[2*kk+1][2], accs[2*kk+1][3], ph[3], pl[3]);
            int vr = kk * 16 + v_row;
            #pragma unroll
            for (int np = 0; np < 8; np++) {
                int n0 = np * 16 + v_csel;
                uint32_t voff = (uint32_t)((n0 >> 6) * 8192 + SWZ128(vr * 128 + (n0 & 63) * 2));
                uint32_t vf[4];
                ldmx4t(vf, sg + ATT_VH + voff);
                mma16816(acco[np * 2],     ph, vf);
                mma16816(acco[np * 2 + 1], ph, vf + 2);
                mma16816(acco[np * 2],     pl, vf);
                mma16816(acco[np * 2 + 1], pl, vf + 2);
            }
            #pragma unroll
            for (int np = 0; np < 8; np++) {
                int n0 = np * 16 + v_csel;
                uint32_t voff = (uint32_t)((n0 >> 6) * 8192 + SWZ128(vr * 128 + (n0 & 63) * 2));
                uint32_t vf[4];
                ldmx4t(vf, sg + ATT_VL + voff);
                mma16816(acco[np * 2],     ph, vf);
                mma16816(acco[np * 2 + 1], ph, vf + 2);
            }
        }
        __syncthreads();
    }

    float inv0 = 1.f / l0, inv1 = 1.f / l1;
    size_t row0 = (size_t)(b * S_LEN + qg0) * D_MODEL + h * D_HEAD;
    size_t row1 = row0 + 8 * D_MODEL;
    #pragma unroll
    for (int nt = 0; nt < 16; nt++) {
        int n = nt * 8 + qcol;
        uint32_t h0, lo0, h1, lo1;
        split_pack(acco[nt][0] * inv0, acco[nt][1] * inv0, h0, lo0);
        split_pack(acco[nt][2] * inv1, acco[nt][3] * inv1, h1, lo1);
        *(uint32_t*)&AVh[row0 + n] = h0;
        *(uint32_t*)&AVl[row0 + n] = lo0;
        *(uint32_t*)&AVh[row1 + n] = h1;
        *(uint32_t*)&AVl[row1 + n] = lo1;
    }
}

// ---------------- launch ----------------
extern "C" void kernel_launch(void* const* d_in, const int* in_sizes, int n_in,
                              void* d_out, int out_size)
{
    const float* X    = (const float*)d_in[0];
    const float* ln_g = (const float*)d_in[1];
    const float* ln_b = (const float*)d_in[2];
    const float* Wq   = (const float*)d_in[3];
    const float* bq   = (const float*)d_in[4];
    const float* Wk   = (const float*)d_in[5];
    const float* bk   = (const float*)d_in[6];
    const float* Wv   = (const float*)d_in[7];
    const float* bv   = (const float*)d_in[8];
    const float* Wo   = (const float*)d_in[9];
    const float* bo   = (const float*)d_in[10];
    float* out = (float*)d_out;

    __nv_bfloat16 *Xh, *Xl, *Qh, *Ql, *Kh, *Kl, *Vh, *Vl, *AVh, *AVl, *Wth, *Wtl;
    cudaGetSymbolAddress((void**)&Xh,  g_Xh);
    cudaGetSymbolAddress((void**)&Xl,  g_Xl);
    cudaGetSymbolAddress((void**)&Qh,  g_Qh);
    cudaGetSymbolAddress((void**)&Ql,  g_Ql);
    cudaGetSymbolAddress((void**)&Kh,  g_Kh);
    cudaGetSymbolAddress((void**)&Kl,  g_Kl);
    cudaGetSymbolAddress((void**)&Vh,  g_Vh);
    cudaGetSymbolAddress((void**)&Vl,  g_Vl);
    cudaGetSymbolAddress((void**)&AVh, g_AVh);
    cudaGetSymbolAddress((void**)&AVl, g_AVl);
    cudaGetSymbolAddress((void**)&Wth, g_Wth);
    cudaGetSymbolAddress((void**)&Wtl, g_Wtl);

    const size_t WSZ = (size_t)D_MODEL * D_MODEL;

    dim3 tg(D_MODEL / 32, D_MODEL / 32, 4);
    transpose_split_kernel<<<tg, 256>>>(Wq, Wk, Wv, Wo, Wth, Wtl);

    ln_split_kernel<<<NROWS, 256>>>(X, ln_g, ln_b, Xh, Xl);

    cudaFuncSetAttribute(gemm_qkv, cudaFuncAttributeMaxDynamicSharedMemorySize, GEMM_SMEM);
    cudaFuncSetAttribute(gemm_out, cudaFuncAttributeMaxDynamicSharedMemorySize, GEMM_SMEM);
    dim3 gq(D_MODEL / 128, NROWS / 128, 3);
    gemm_qkv<<<gq, 256, GEMM_SMEM>>>(Xh, Xl, Wth, Wtl, bq, bk, bv,
                                     Qh, Ql, Kh, Kl, Vh, Vl);

    cudaFuncSetAttribute(attn_hmma, cudaFuncAttributeMaxDynamicSharedMemorySize, ATTN_SMEM);
    attn_hmma<<<dim3(S_LEN / 128, BATCH * N_HEADS), 256, ATTN_SMEM>>>(
        Qh, Ql, Kh, Kl, Vh, Vl, AVh, AVl);

    dim3 gg(D_MODEL / 128, NROWS / 128);
    gemm_out<<<gg, 256, GEMM_SMEM>>>(AVh, AVl, Wth + 3 * WSZ, Wtl + 3 * WSZ, bo, out);
}